// round 1
// baseline (speedup 1.0000x reference)
#include <cuda_runtime.h>

#define N_TOK 4096
#define DM    1024
#define NE    64
#define CAP   512

// ---- scratch (device globals; no allocation allowed) ----
__device__ int   g_cnt[NE];
__device__ int   g_topE[N_TOK * 2];
__device__ float g_topW[N_TOK * 2];
__device__ int   g_tokid[NE * CAP];
__device__ float g_tokw[NE * CAP];
__device__ float g_logits[N_TOK * NE];

// ---------------------------------------------------------
__global__ void k_init() {
    if (threadIdx.x < NE) g_cnt[threadIdx.x] = 0;
}

// ---- gating GEMM: logits[N,E] = x[N,D] @ gate_w[E,D]^T ----
#define BK  16
#define SMS 68   // padded row stride for transposed smem tiles

__global__ __launch_bounds__(256) void k_gate(const float* __restrict__ x,
                                              const float* __restrict__ gw) {
    __shared__ float As[BK][SMS];
    __shared__ float Bs[BK][SMS];
    int t  = threadIdx.x;
    int lr = t >> 2;            // 0..63 row within tile
    int lc = (t & 3) << 2;      // 0,4,8,12
    int m0 = blockIdx.x * 64;
    const float* aptr = x  + (size_t)(m0 + lr) * DM;
    const float* bptr = gw + (size_t)lr * DM;    // BN=64 == NE, n0=0
    int ty = t >> 4, tx = t & 15;
    float acc[4][4] = {};

    for (int k0 = 0; k0 < DM; k0 += BK) {
        float4 av = *(const float4*)(aptr + k0 + lc);
        float4 bv = *(const float4*)(bptr + k0 + lc);
        __syncthreads();
        As[lc][lr] = av.x; As[lc + 1][lr] = av.y; As[lc + 2][lr] = av.z; As[lc + 3][lr] = av.w;
        Bs[lc][lr] = bv.x; Bs[lc + 1][lr] = bv.y; Bs[lc + 2][lr] = bv.z; Bs[lc + 3][lr] = bv.w;
        __syncthreads();
#pragma unroll
        for (int kk = 0; kk < BK; kk++) {
            float4 a4 = *(const float4*)&As[kk][ty * 4];
            float4 b4 = *(const float4*)&Bs[kk][tx * 4];
            float a[4] = {a4.x, a4.y, a4.z, a4.w};
            float b[4] = {b4.x, b4.y, b4.z, b4.w};
#pragma unroll
            for (int i = 0; i < 4; i++)
#pragma unroll
                for (int j = 0; j < 4; j++) acc[i][j] += a[i] * b[j];
        }
    }
#pragma unroll
    for (int i = 0; i < 4; i++) {
        int m = m0 + ty * 4 + i;
        *(float4*)&g_logits[m * NE + tx * 4] =
            make_float4(acc[i][0], acc[i][1], acc[i][2], acc[i][3]);
    }
}

// ---- top-2 + softmax: one warp per token ----
__global__ void k_top2() {
    int gid  = blockIdx.x * blockDim.x + threadIdx.x;
    int tokn = gid >> 5;
    int lane = threadIdx.x & 31;
    if (tokn >= N_TOK) return;
    const float* lg = g_logits + tokn * NE;
    float a = lg[lane], b = lg[lane + 32];
    float v1, v2; int i1, i2;
    if (a >= b) { v1 = a; i1 = lane;      v2 = b; i2 = lane + 32; }
    else        { v1 = b; i1 = lane + 32; v2 = a; i2 = lane;      }
#pragma unroll
    for (int off = 16; off > 0; off >>= 1) {
        float ov1 = __shfl_xor_sync(0xffffffffu, v1, off);
        int   oi1 = __shfl_xor_sync(0xffffffffu, i1, off);
        float ov2 = __shfl_xor_sync(0xffffffffu, v2, off);
        int   oi2 = __shfl_xor_sync(0xffffffffu, i2, off);
        bool og = (ov1 > v1) || (ov1 == v1 && oi1 < i1);
        if (og) {
            bool sg = (v1 > ov2) || (v1 == ov2 && i1 < oi2);
            if (sg) { v2 = v1; i2 = i1; } else { v2 = ov2; i2 = oi2; }
            v1 = ov1; i1 = oi1;
        } else {
            bool sg = (ov1 > v2) || (ov1 == v2 && oi1 < i2);
            if (sg) { v2 = ov1; i2 = oi1; }
        }
    }
    if (lane == 0) {
        float e  = expf(v2 - v1);          // <= 0 exponent, stable
        float w1 = 1.0f / (1.0f + e);
        g_topE[tokn * 2]     = i1;
        g_topE[tokn * 2 + 1] = i2;
        g_topW[tokn * 2]     = w1;
        g_topW[tokn * 2 + 1] = e * w1;     // e/(1+e)
    }
}

// ---- dispatch: build per-expert token lists ----
__global__ void k_scatter() {
    int s = blockIdx.x * blockDim.x + threadIdx.x;
    if (s >= N_TOK * 2) return;
    int e   = g_topE[s];
    int pos = atomicAdd(&g_cnt[e], 1);
    if (pos < CAP) {
        g_tokid[e * CAP + pos] = s >> 1;
        g_tokw [e * CAP + pos] = g_topW[s];
    }
}

// ---- grouped expert GEMM: Y = gather(x) @ W_e^T, combine via atomicAdd ----
__global__ __launch_bounds__(256) void k_moe(const float* __restrict__ x,
                                             const float* __restrict__ ew,
                                             float* __restrict__ out) {
    __shared__ float As[BK][SMS];
    __shared__ float Bs[BK][SMS];
    int e   = blockIdx.x >> 3;           // CAP/64 = 8 M-tiles per expert
    int mt  = blockIdx.x & 7;
    int cnt = min(g_cnt[e], CAP);
    int row0 = mt << 6;
    if (row0 >= cnt) return;             // empty tile -> exit
    int n0 = blockIdx.y << 6;

    int t  = threadIdx.x;
    int lr = t >> 2;
    int lc = (t & 3) << 2;
    int ar  = row0 + lr;
    int tok = (ar < cnt) ? g_tokid[e * CAP + ar] : -1;
    const float* aptr = x + (size_t)(tok < 0 ? 0 : tok) * DM;
    const float* bptr = ew + (size_t)e * DM * DM + (size_t)(n0 + lr) * DM;
    int ty = t >> 4, tx = t & 15;
    float acc[4][4] = {};

    for (int k0 = 0; k0 < DM; k0 += BK) {
        float4 av = (tok >= 0) ? *(const float4*)(aptr + k0 + lc)
                               : make_float4(0.f, 0.f, 0.f, 0.f);
        float4 bv = *(const float4*)(bptr + k0 + lc);
        __syncthreads();
        As[lc][lr] = av.x; As[lc + 1][lr] = av.y; As[lc + 2][lr] = av.z; As[lc + 3][lr] = av.w;
        Bs[lc][lr] = bv.x; Bs[lc + 1][lr] = bv.y; Bs[lc + 2][lr] = bv.z; Bs[lc + 3][lr] = bv.w;
        __syncthreads();
#pragma unroll
        for (int kk = 0; kk < BK; kk++) {
            float4 a4 = *(const float4*)&As[kk][ty * 4];
            float4 b4 = *(const float4*)&Bs[kk][tx * 4];
            float a[4] = {a4.x, a4.y, a4.z, a4.w};
            float b[4] = {b4.x, b4.y, b4.z, b4.w};
#pragma unroll
            for (int i = 0; i < 4; i++)
#pragma unroll
                for (int j = 0; j < 4; j++) acc[i][j] += a[i] * b[j];
        }
    }

    int nb = n0 + tx * 4;
#pragma unroll
    for (int i = 0; i < 4; i++) {
        int r = row0 + ty * 4 + i;
        if (r < cnt) {
            int   tk = g_tokid[e * CAP + r];
            float w  = g_tokw [e * CAP + r];
            float* o = out + (size_t)tk * DM + nb;
            atomicAdd(o + 0, w * acc[i][0]);
            atomicAdd(o + 1, w * acc[i][1]);
            atomicAdd(o + 2, w * acc[i][2]);
            atomicAdd(o + 3, w * acc[i][3]);
        }
    }
}

// ---------------------------------------------------------
extern "C" void kernel_launch(void* const* d_in, const int* in_sizes, int n_in,
                              void* d_out, int out_size) {
    const float* x  = (const float*)d_in[0];   // [4096,1024]
    const float* gw = (const float*)d_in[1];   // [64,1024]
    const float* ew = (const float*)d_in[2];   // [64,1024,1024]
    float* out = (float*)d_out;                // [4096,1024]

    cudaMemsetAsync(d_out, 0, (size_t)N_TOK * DM * sizeof(float), 0);
    k_init<<<1, 64>>>();
    k_gate<<<N_TOK / 64, 256>>>(x, gw);
    k_top2<<<N_TOK / 8, 256>>>();
    k_scatter<<<(N_TOK * 2) / 256, 256>>>();
    dim3 grid(NE * 8, DM / 64);
    k_moe<<<grid, 256>>>(x, ew, out);
    (void)in_sizes; (void)n_in; (void)out_size; (void)out;
}

// round 3
// speedup vs baseline: 1.1178x; 1.1178x over previous
#include <cuda_runtime.h>
#include <cuda_bf16.h>
#include <cstdint>

#define N_TOK 4096
#define DM    1024
#define NE    64
#define CAP   512

// ---- scratch (device globals; no allocation allowed) ----
__device__ int   g_cnt[NE];
__device__ int   g_topE[N_TOK * 2];
__device__ float g_topW[N_TOK * 2];
__device__ int   g_tokid[NE * CAP];
__device__ float g_tokw[NE * CAP];
__device__ float g_logits[N_TOK * NE];

// ---------------------------------------------------------
__global__ void k_init() {
    if (threadIdx.x < NE) g_cnt[threadIdx.x] = 0;
}

// ---- gating GEMM: logits[N,E] = x[N,D] @ gate_w[E,D]^T (fp32 SIMT) ----
#define BK  16
#define SMS 68

__global__ __launch_bounds__(256) void k_gate(const float* __restrict__ x,
                                              const float* __restrict__ gw) {
    __shared__ float As[BK][SMS];
    __shared__ float Bs[BK][SMS];
    int t  = threadIdx.x;
    int lr = t >> 2;
    int lc = (t & 3) << 2;
    int m0 = blockIdx.x * 64;
    const float* aptr = x  + (size_t)(m0 + lr) * DM;
    const float* bptr = gw + (size_t)lr * DM;
    int ty = t >> 4, tx = t & 15;
    float acc[4][4] = {};

    for (int k0 = 0; k0 < DM; k0 += BK) {
        float4 av = *(const float4*)(aptr + k0 + lc);
        float4 bv = *(const float4*)(bptr + k0 + lc);
        __syncthreads();
        As[lc][lr] = av.x; As[lc + 1][lr] = av.y; As[lc + 2][lr] = av.z; As[lc + 3][lr] = av.w;
        Bs[lc][lr] = bv.x; Bs[lc + 1][lr] = bv.y; Bs[lc + 2][lr] = bv.z; Bs[lc + 3][lr] = bv.w;
        __syncthreads();
#pragma unroll
        for (int kk = 0; kk < BK; kk++) {
            float4 a4 = *(const float4*)&As[kk][ty * 4];
            float4 b4 = *(const float4*)&Bs[kk][tx * 4];
            float a[4] = {a4.x, a4.y, a4.z, a4.w};
            float b[4] = {b4.x, b4.y, b4.z, b4.w};
#pragma unroll
            for (int i = 0; i < 4; i++)
#pragma unroll
                for (int j = 0; j < 4; j++) acc[i][j] += a[i] * b[j];
        }
    }
#pragma unroll
    for (int i = 0; i < 4; i++) {
        int m = m0 + ty * 4 + i;
        *(float4*)&g_logits[m * NE + tx * 4] =
            make_float4(acc[i][0], acc[i][1], acc[i][2], acc[i][3]);
    }
}

// ---- top-2 + softmax: one warp per token ----
__global__ void k_top2() {
    int gid  = blockIdx.x * blockDim.x + threadIdx.x;
    int tokn = gid >> 5;
    int lane = threadIdx.x & 31;
    if (tokn >= N_TOK) return;
    const float* lg = g_logits + tokn * NE;
    float a = lg[lane], b = lg[lane + 32];
    float v1, v2; int i1, i2;
    if (a >= b) { v1 = a; i1 = lane;      v2 = b; i2 = lane + 32; }
    else        { v1 = b; i1 = lane + 32; v2 = a; i2 = lane;      }
#pragma unroll
    for (int off = 16; off > 0; off >>= 1) {
        float ov1 = __shfl_xor_sync(0xffffffffu, v1, off);
        int   oi1 = __shfl_xor_sync(0xffffffffu, i1, off);
        float ov2 = __shfl_xor_sync(0xffffffffu, v2, off);
        int   oi2 = __shfl_xor_sync(0xffffffffu, i2, off);
        bool og = (ov1 > v1) || (ov1 == v1 && oi1 < i1);
        if (og) {
            bool sg = (v1 > ov2) || (v1 == ov2 && i1 < oi2);
            if (sg) { v2 = v1; i2 = i1; } else { v2 = ov2; i2 = oi2; }
            v1 = ov1; i1 = oi1;
        } else {
            bool sg = (ov1 > v2) || (ov1 == v2 && oi1 < i2);
            if (sg) { v2 = ov1; i2 = oi1; }
        }
    }
    if (lane == 0) {
        float e  = expf(v2 - v1);
        float w1 = 1.0f / (1.0f + e);
        g_topE[tokn * 2]     = i1;
        g_topE[tokn * 2 + 1] = i2;
        g_topW[tokn * 2]     = w1;
        g_topW[tokn * 2 + 1] = e * w1;
    }
}

// ---- dispatch: build per-expert token lists ----
__global__ void k_scatter() {
    int s = blockIdx.x * blockDim.x + threadIdx.x;
    if (s >= N_TOK * 2) return;
    int e   = g_topE[s];
    int pos = atomicAdd(&g_cnt[e], 1);
    if (pos < CAP) {
        g_tokid[e * CAP + pos] = s >> 1;
        g_tokw [e * CAP + pos] = g_topW[s];
    }
}

// =========================================================
// mma.sync bf16 split-precision grouped expert GEMM
// D = (xh+xl)(wh+wl)^T ~= xh*wh + xh*wl + xl*wh  (fp32 accum)
// CTA tile 128x128, K-chunk 64, 8 warps (2x4), warp tile 64x32.
// SW128-swizzled smem, double-buffered, prefetch interleaved.
// =========================================================

#define SWZ(o) ((o) ^ (((o) >> 3) & 0x70))

#define LDSM4(r0, r1, r2, r3, a)                                             \
    asm volatile("ldmatrix.sync.aligned.m8n8.x4.shared.b16 {%0,%1,%2,%3}, [%4];" \
                 : "=r"(r0), "=r"(r1), "=r"(r2), "=r"(r3) : "r"(a))

#define MMA(d, a, b0, b1)                                                     \
    asm volatile("mma.sync.aligned.m16n8k16.row.col.f32.bf16.bf16.f32 "       \
                 "{%0,%1,%2,%3},{%4,%5,%6,%7},{%8,%9},{%0,%1,%2,%3};"         \
                 : "+f"((d)[0]), "+f"((d)[1]), "+f"((d)[2]), "+f"((d)[3])     \
                 : "r"((a)[0]), "r"((a)[1]), "r"((a)[2]), "r"((a)[3]),        \
                   "r"(b0), "r"(b1))

__device__ __forceinline__ uint32_t pk(float a, float b) {
    __nv_bfloat162 h = __floats2bfloat162_rn(a, b);
    return *(uint32_t*)&h;
}

// per-buffer region offsets (bytes): Ah, Al, Bh, Bl each 16KB
#define R_AL 16384
#define R_BH 32768
#define R_BL 49152
#define BUFB 65536
#define SMEM_MOE (1024 + 2 * BUFB)

// prefetch one group (2 float4 of A + 2 of B per thread) for chunk at k0f
__device__ __forceinline__ void pf_group(const float* __restrict__ x,
                                         const float* __restrict__ wbase,
                                         const int* __restrict__ toks,
                                         char* __restrict__ pb,
                                         int k0f, int g, int tid) {
#pragma unroll
    for (int u = 0; u < 2; u++) {
        int idx = ((g * 2 + u) << 8) + tid;
        int row = idx >> 4, kg = idx & 15;
        int tk  = toks[row];
        float4 av = (tk >= 0) ? *(const float4*)(x + (size_t)tk * DM + k0f + (kg << 2))
                              : make_float4(0.f, 0.f, 0.f, 0.f);
        float4 bv = *(const float4*)(wbase + (size_t)row * DM + k0f + (kg << 2));
        uint32_t off = SWZ((uint32_t)((row << 7) | (kg << 3)));

        float ax = __bfloat162float(__float2bfloat16_rn(av.x));
        float ay = __bfloat162float(__float2bfloat16_rn(av.y));
        float az = __bfloat162float(__float2bfloat16_rn(av.z));
        float aw = __bfloat162float(__float2bfloat16_rn(av.w));
        *(uint2*)(pb + off)        = make_uint2(pk(av.x, av.y), pk(av.z, av.w));
        *(uint2*)(pb + R_AL + off) = make_uint2(pk(av.x - ax, av.y - ay), pk(av.z - az, av.w - aw));

        float bx = __bfloat162float(__float2bfloat16_rn(bv.x));
        float by = __bfloat162float(__float2bfloat16_rn(bv.y));
        float bz = __bfloat162float(__float2bfloat16_rn(bv.z));
        float bw = __bfloat162float(__float2bfloat16_rn(bv.w));
        *(uint2*)(pb + R_BH + off) = make_uint2(pk(bv.x, bv.y), pk(bv.z, bv.w));
        *(uint2*)(pb + R_BL + off) = make_uint2(pk(bv.x - bx, bv.y - by), pk(bv.z - bz, bv.w - bw));
    }
}

__global__ __launch_bounds__(256, 1) void k_moe(const float* __restrict__ x,
                                                const float* __restrict__ ew,
                                                float* __restrict__ out) {
    extern __shared__ __align__(1024) char smem[];
    int*   toks = (int*)smem;            // 512 B
    float* wts  = (float*)(smem + 512);  // 512 B
    char*  buf  = smem + 1024;           // 2 x 64 KB

    int e    = blockIdx.x >> 2;
    int mt   = blockIdx.x & 3;
    int cnt  = min(g_cnt[e], CAP);
    int row0 = mt << 7;
    if (row0 >= cnt) return;
    int n0   = blockIdx.y << 7;

    int tid = threadIdx.x, lane = tid & 31, wid = tid >> 5;
    int mw = wid & 1, nw = wid >> 1;

    if (tid < 128) {
        int r = row0 + tid;
        bool v = r < cnt;
        toks[tid] = v ? g_tokid[e * CAP + r] : -1;
        wts[tid]  = v ? g_tokw[e * CAP + r] : 0.0f;
    }
    __syncthreads();

    const float* wbase = ew + (size_t)e * DM * DM + (size_t)n0 * DM;

    uint32_t sbuf;
    asm("{ .reg .u64 t; cvta.to.shared.u64 t, %1; cvt.u32.u64 %0, t; }"
        : "=r"(sbuf) : "l"(buf));

    // ldmatrix per-lane row offsets (bytes within a 16KB region)
    uint32_t a_ro = (uint32_t)(((mw << 6) + (lane & 15)) << 7) + (uint32_t)((lane >> 4) << 4);
    uint32_t b_ro = (uint32_t)(((nw << 5) + (lane & 7) + ((lane >> 4) << 3)) << 7)
                  + (uint32_t)(((lane >> 3) & 1) << 4);

    float acc[4][4][4];
#pragma unroll
    for (int i = 0; i < 4; i++)
#pragma unroll
        for (int j = 0; j < 4; j++)
#pragma unroll
            for (int q = 0; q < 4; q++) acc[i][j][q] = 0.0f;

    // initial prefetch: chunk 0 -> buffer 0
#pragma unroll
    for (int g = 0; g < 4; g++) pf_group(x, wbase, toks, buf, 0, g, tid);
    __syncthreads();

    for (int c = 0; c < 16; c++) {
        uint32_t cb = sbuf + (uint32_t)(c & 1) * BUFB;   // compute buffer (smem addr)
        char*    pb = buf + ((c + 1) & 1) * BUFB;        // prefetch buffer (ptr)
        int  k0f = (c + 1) << 6;
        bool pf  = (c < 15);

#pragma unroll
        for (int ks = 0; ks < 4; ks++) {
            if (pf) pf_group(x, wbase, toks, pb, k0f, ks, tid);

            uint32_t kb = (uint32_t)(ks << 5);   // 16 bf16 = 32 bytes per k-step
            uint32_t bh[8], bl[8];
#pragma unroll
            for (int j2 = 0; j2 < 2; j2++) {
                uint32_t o = SWZ(b_ro + (uint32_t)(j2 << 11) + kb);
                LDSM4(bh[j2 * 4], bh[j2 * 4 + 1], bh[j2 * 4 + 2], bh[j2 * 4 + 3], cb + R_BH + o);
                LDSM4(bl[j2 * 4], bl[j2 * 4 + 1], bl[j2 * 4 + 2], bl[j2 * 4 + 3], cb + R_BL + o);
            }
#pragma unroll
            for (int i = 0; i < 4; i++) {
                uint32_t o = SWZ(a_ro + (uint32_t)(i << 11) + kb);
                uint32_t ah[4], al[4];
                LDSM4(ah[0], ah[1], ah[2], ah[3], cb + o);
                LDSM4(al[0], al[1], al[2], al[3], cb + R_AL + o);
#pragma unroll
                for (int j = 0; j < 4; j++) {
                    MMA(acc[i][j], ah, bh[j * 2], bh[j * 2 + 1]);  // hh
                    MMA(acc[i][j], ah, bl[j * 2], bl[j * 2 + 1]);  // hl
                    MMA(acc[i][j], al, bh[j * 2], bh[j * 2 + 1]);  // lh
                }
            }
        }
        __syncthreads();
    }

    // ---- epilogue: scale by gate weight, atomicAdd combine ----
    int l4 = lane >> 2;
    int l2 = (lane & 3) << 1;
#pragma unroll
    for (int i = 0; i < 4; i++) {
        int r0 = (mw << 6) + (i << 4) + l4;
        int r1 = r0 + 8;
        int   tk0 = toks[r0]; float w0 = wts[r0];
        int   tk1 = toks[r1]; float w1 = wts[r1];
        float* o0 = out + (size_t)(tk0 < 0 ? 0 : tk0) * DM;
        float* o1 = out + (size_t)(tk1 < 0 ? 0 : tk1) * DM;
#pragma unroll
        for (int j = 0; j < 4; j++) {
            int nb = n0 + (nw << 5) + (j << 3) + l2;
            if (tk0 >= 0) {
                atomicAdd(o0 + nb,     w0 * acc[i][j][0]);
                atomicAdd(o0 + nb + 1, w0 * acc[i][j][1]);
            }
            if (tk1 >= 0) {
                atomicAdd(o1 + nb,     w1 * acc[i][j][2]);
                atomicAdd(o1 + nb + 1, w1 * acc[i][j][3]);
            }
        }
    }
}

// ---------------------------------------------------------
extern "C" void kernel_launch(void* const* d_in, const int* in_sizes, int n_in,
                              void* d_out, int out_size) {
    const float* x  = (const float*)d_in[0];   // [4096,1024]
    const float* gw = (const float*)d_in[1];   // [64,1024]
    const float* ew = (const float*)d_in[2];   // [64,1024,1024]
    float* out = (float*)d_out;                // [4096,1024]

    cudaFuncSetAttribute(k_moe, cudaFuncAttributeMaxDynamicSharedMemorySize, SMEM_MOE);

    cudaMemsetAsync(d_out, 0, (size_t)N_TOK * DM * sizeof(float), 0);
    k_init<<<1, 64>>>();
    k_gate<<<N_TOK / 64, 256>>>(x, gw);
    k_top2<<<N_TOK / 8, 256>>>();
    k_scatter<<<(N_TOK * 2) / 256, 256>>>();
    dim3 grid(NE * 4, DM / 128);
    k_moe<<<grid, 256, SMEM_MOE>>>(x, ew, out);
    (void)in_sizes; (void)n_in; (void)out_size; (void)out;
}

// round 4
// speedup vs baseline: 1.9087x; 1.7076x over previous
#include <cuda_runtime.h>
#include <cuda_fp16.h>
#include <cuda_bf16.h>
#include <cstdint>

#define N_TOK 4096
#define DM    1024
#define NE    64
#define CAP   512

// ---- scratch (device globals; no allocation allowed) ----
__device__ int   g_cnt[NE];
__device__ int   g_topE[N_TOK * 2];
__device__ float g_topW[N_TOK * 2];
__device__ int   g_tokid[NE * CAP];
__device__ float g_tokw[NE * CAP];
__device__ float g_logits[N_TOK * NE];

// ---------------------------------------------------------
__global__ void k_init() {
    if (threadIdx.x < NE) g_cnt[threadIdx.x] = 0;
}

// ---- gating GEMM: logits[N,E] = x[N,D] @ gate_w[E,D]^T (fp32 SIMT, exact) ----
#define BK  16
#define SMS 68

__global__ __launch_bounds__(256) void k_gate(const float* __restrict__ x,
                                              const float* __restrict__ gw) {
    __shared__ float As[BK][SMS];
    __shared__ float Bs[BK][SMS];
    int t  = threadIdx.x;
    int lr = t >> 2;
    int lc = (t & 3) << 2;
    int m0 = blockIdx.x * 64;
    const float* aptr = x  + (size_t)(m0 + lr) * DM;
    const float* bptr = gw + (size_t)lr * DM;
    int ty = t >> 4, tx = t & 15;
    float acc[4][4] = {};

    for (int k0 = 0; k0 < DM; k0 += BK) {
        float4 av = *(const float4*)(aptr + k0 + lc);
        float4 bv = *(const float4*)(bptr + k0 + lc);
        __syncthreads();
        As[lc][lr] = av.x; As[lc + 1][lr] = av.y; As[lc + 2][lr] = av.z; As[lc + 3][lr] = av.w;
        Bs[lc][lr] = bv.x; Bs[lc + 1][lr] = bv.y; Bs[lc + 2][lr] = bv.z; Bs[lc + 3][lr] = bv.w;
        __syncthreads();
#pragma unroll
        for (int kk = 0; kk < BK; kk++) {
            float4 a4 = *(const float4*)&As[kk][ty * 4];
            float4 b4 = *(const float4*)&Bs[kk][tx * 4];
            float a[4] = {a4.x, a4.y, a4.z, a4.w};
            float b[4] = {b4.x, b4.y, b4.z, b4.w};
#pragma unroll
            for (int i = 0; i < 4; i++)
#pragma unroll
                for (int j = 0; j < 4; j++) acc[i][j] += a[i] * b[j];
        }
    }
#pragma unroll
    for (int i = 0; i < 4; i++) {
        int m = m0 + ty * 4 + i;
        *(float4*)&g_logits[m * NE + tx * 4] =
            make_float4(acc[i][0], acc[i][1], acc[i][2], acc[i][3]);
    }
}

// ---- top-2 + softmax: one warp per token ----
__global__ void k_top2() {
    int gid  = blockIdx.x * blockDim.x + threadIdx.x;
    int tokn = gid >> 5;
    int lane = threadIdx.x & 31;
    if (tokn >= N_TOK) return;
    const float* lg = g_logits + tokn * NE;
    float a = lg[lane], b = lg[lane + 32];
    float v1, v2; int i1, i2;
    if (a >= b) { v1 = a; i1 = lane;      v2 = b; i2 = lane + 32; }
    else        { v1 = b; i1 = lane + 32; v2 = a; i2 = lane;      }
#pragma unroll
    for (int off = 16; off > 0; off >>= 1) {
        float ov1 = __shfl_xor_sync(0xffffffffu, v1, off);
        int   oi1 = __shfl_xor_sync(0xffffffffu, i1, off);
        float ov2 = __shfl_xor_sync(0xffffffffu, v2, off);
        int   oi2 = __shfl_xor_sync(0xffffffffu, i2, off);
        bool og = (ov1 > v1) || (ov1 == v1 && oi1 < i1);
        if (og) {
            bool sg = (v1 > ov2) || (v1 == ov2 && i1 < oi2);
            if (sg) { v2 = v1; i2 = i1; } else { v2 = ov2; i2 = oi2; }
            v1 = ov1; i1 = oi1;
        } else {
            bool sg = (ov1 > v2) || (ov1 == v2 && oi1 < i2);
            if (sg) { v2 = ov1; i2 = oi1; }
        }
    }
    if (lane == 0) {
        float e  = expf(v2 - v1);
        float w1 = 1.0f / (1.0f + e);
        g_topE[tokn * 2]     = i1;
        g_topE[tokn * 2 + 1] = i2;
        g_topW[tokn * 2]     = w1;
        g_topW[tokn * 2 + 1] = e * w1;
    }
}

// ---- dispatch: build per-expert token lists ----
__global__ void k_scatter() {
    int s = blockIdx.x * blockDim.x + threadIdx.x;
    if (s >= N_TOK * 2) return;
    int e   = g_topE[s];
    int pos = atomicAdd(&g_cnt[e], 1);
    if (pos < CAP) {
        g_tokid[e * CAP + pos] = s >> 1;
        g_tokw [e * CAP + pos] = g_topW[s];
    }
}

// =========================================================
// mma.sync fp16 grouped expert GEMM (single product, fp32 accum)
// CTA tile 128x128, K-chunk 64, 8 warps (2x4), warp tile 64x32.
// SW128-swizzled smem, double-buffered, prefetch interleaved,
// 65 KB smem -> 2 CTAs/SM.
// =========================================================

#define SWZ(o) ((o) ^ (((o) >> 3) & 0x70))

#define LDSM4(r0, r1, r2, r3, a)                                             \
    asm volatile("ldmatrix.sync.aligned.m8n8.x4.shared.b16 {%0,%1,%2,%3}, [%4];" \
                 : "=r"(r0), "=r"(r1), "=r"(r2), "=r"(r3) : "r"(a))

#define MMA(d, a, b0, b1)                                                     \
    asm volatile("mma.sync.aligned.m16n8k16.row.col.f32.f16.f16.f32 "         \
                 "{%0,%1,%2,%3},{%4,%5,%6,%7},{%8,%9},{%0,%1,%2,%3};"         \
                 : "+f"((d)[0]), "+f"((d)[1]), "+f"((d)[2]), "+f"((d)[3])     \
                 : "r"((a)[0]), "r"((a)[1]), "r"((a)[2]), "r"((a)[3]),        \
                   "r"(b0), "r"(b1))

__device__ __forceinline__ uint32_t pkh(float a, float b) {
    __half2 h = __floats2half2_rn(a, b);
    return *(uint32_t*)&h;
}

// per-buffer regions (bytes): A 16KB, B 16KB
#define R_B   16384
#define BUFB  32768
#define SMEM_MOE (1024 + 2 * BUFB)   // 66560

// prefetch one group: 2 float4 of A + 2 of B per thread, converted to fp16
__device__ __forceinline__ void pf_group(const float* __restrict__ x,
                                         const float* __restrict__ wbase,
                                         const int* __restrict__ toks,
                                         char* __restrict__ pb,
                                         int k0f, int g, int tid) {
#pragma unroll
    for (int u = 0; u < 2; u++) {
        int idx = ((g * 2 + u) << 8) + tid;      // 0..2047
        int row = idx >> 4, kg = idx & 15;
        int tk  = toks[row];
        float4 av = (tk >= 0) ? *(const float4*)(x + (size_t)tk * DM + k0f + (kg << 2))
                              : make_float4(0.f, 0.f, 0.f, 0.f);
        float4 bv = *(const float4*)(wbase + (size_t)row * DM + k0f + (kg << 2));
        uint32_t off = SWZ((uint32_t)((row << 7) | (kg << 3)));
        *(uint2*)(pb + off)       = make_uint2(pkh(av.x, av.y), pkh(av.z, av.w));
        *(uint2*)(pb + R_B + off) = make_uint2(pkh(bv.x, bv.y), pkh(bv.z, bv.w));
    }
}

__global__ __launch_bounds__(256, 2) void k_moe(const float* __restrict__ x,
                                                const float* __restrict__ ew,
                                                float* __restrict__ out) {
    extern __shared__ __align__(1024) char smem[];
    int*   toks = (int*)smem;            // 512 B
    float* wts  = (float*)(smem + 512);  // 512 B
    char*  buf  = smem + 1024;           // 2 x 32 KB

    int e    = blockIdx.x >> 2;
    int mt   = blockIdx.x & 3;
    int cnt  = min(g_cnt[e], CAP);
    int row0 = mt << 7;
    if (row0 >= cnt) return;
    int n0   = blockIdx.y << 7;

    int tid = threadIdx.x, lane = tid & 31, wid = tid >> 5;
    int mw = wid & 1, nw = wid >> 1;

    if (tid < 128) {
        int r = row0 + tid;
        bool v = r < cnt;
        toks[tid] = v ? g_tokid[e * CAP + r] : -1;
        wts[tid]  = v ? g_tokw[e * CAP + r] : 0.0f;
    }
    __syncthreads();

    const float* wbase = ew + (size_t)e * DM * DM + (size_t)n0 * DM;

    uint32_t sbuf;
    asm("{ .reg .u64 t; cvta.to.shared.u64 t, %1; cvt.u32.u64 %0, t; }"
        : "=r"(sbuf) : "l"(buf));

    // ldmatrix per-lane row offsets (bytes within a 16KB region) — validated in R3
    uint32_t a_ro = (uint32_t)(((mw << 6) + (lane & 15)) << 7) + (uint32_t)((lane >> 4) << 4);
    uint32_t b_ro = (uint32_t)(((nw << 5) + (lane & 7) + ((lane >> 4) << 3)) << 7)
                  + (uint32_t)(((lane >> 3) & 1) << 4);

    float acc[4][4][4];
#pragma unroll
    for (int i = 0; i < 4; i++)
#pragma unroll
        for (int j = 0; j < 4; j++)
#pragma unroll
            for (int q = 0; q < 4; q++) acc[i][j][q] = 0.0f;

    // initial prefetch: chunk 0 -> buffer 0
#pragma unroll
    for (int g = 0; g < 4; g++) pf_group(x, wbase, toks, buf, 0, g, tid);
    __syncthreads();

    for (int c = 0; c < 16; c++) {
        uint32_t cb = sbuf + (uint32_t)(c & 1) * BUFB;   // compute buffer
        char*    pb = buf + ((c + 1) & 1) * BUFB;        // prefetch buffer
        int  k0f = (c + 1) << 6;
        bool pf  = (c < 15);

#pragma unroll
        for (int ks = 0; ks < 4; ks++) {
            if (pf) pf_group(x, wbase, toks, pb, k0f, ks, tid);

            uint32_t kb = (uint32_t)(ks << 5);   // 16 halfs = 32 bytes per k-step
            uint32_t bh[8];
#pragma unroll
            for (int j2 = 0; j2 < 2; j2++) {
                uint32_t o = SWZ(b_ro + (uint32_t)(j2 << 11) + kb);
                LDSM4(bh[j2 * 4], bh[j2 * 4 + 1], bh[j2 * 4 + 2], bh[j2 * 4 + 3],
                      cb + R_B + o);
            }
#pragma unroll
            for (int i = 0; i < 4; i++) {
                uint32_t o = SWZ(a_ro + (uint32_t)(i << 11) + kb);
                uint32_t ah[4];
                LDSM4(ah[0], ah[1], ah[2], ah[3], cb + o);
#pragma unroll
                for (int j = 0; j < 4; j++)
                    MMA(acc[i][j], ah, bh[j * 2], bh[j * 2 + 1]);
            }
        }
        __syncthreads();
    }

    // ---- epilogue: scale by gate weight, atomicAdd combine ----
    int l4 = lane >> 2;
    int l2 = (lane & 3) << 1;
#pragma unroll
    for (int i = 0; i < 4; i++) {
        int r0 = (mw << 6) + (i << 4) + l4;
        int r1 = r0 + 8;
        int   tk0 = toks[r0]; float w0 = wts[r0];
        int   tk1 = toks[r1]; float w1 = wts[r1];
        float* o0 = out + (size_t)(tk0 < 0 ? 0 : tk0) * DM;
        float* o1 = out + (size_t)(tk1 < 0 ? 0 : tk1) * DM;
#pragma unroll
        for (int j = 0; j < 4; j++) {
            int nb = n0 + (nw << 5) + (j << 3) + l2;
            if (tk0 >= 0) {
                atomicAdd(o0 + nb,     w0 * acc[i][j][0]);
                atomicAdd(o0 + nb + 1, w0 * acc[i][j][1]);
            }
            if (tk1 >= 0) {
                atomicAdd(o1 + nb,     w1 * acc[i][j][2]);
                atomicAdd(o1 + nb + 1, w1 * acc[i][j][3]);
            }
        }
    }
}

// ---------------------------------------------------------
extern "C" void kernel_launch(void* const* d_in, const int* in_sizes, int n_in,
                              void* d_out, int out_size) {
    const float* x  = (const float*)d_in[0];   // [4096,1024]
    const float* gw = (const float*)d_in[1];   // [64,1024]
    const float* ew = (const float*)d_in[2];   // [64,1024,1024]
    float* out = (float*)d_out;                // [4096,1024]

    cudaFuncSetAttribute(k_moe, cudaFuncAttributeMaxDynamicSharedMemorySize, SMEM_MOE);

    cudaMemsetAsync(d_out, 0, (size_t)N_TOK * DM * sizeof(float), 0);
    k_init<<<1, 64>>>();
    k_gate<<<N_TOK / 64, 256>>>(x, gw);
    k_top2<<<N_TOK / 8, 256>>>();
    k_scatter<<<(N_TOK * 2) / 256, 256>>>();
    dim3 grid(NE * 4, DM / 128);
    k_moe<<<grid, 256, SMEM_MOE>>>(x, ew, out);
    (void)in_sizes; (void)n_in; (void)out_size; (void)out;
}

// round 5
// speedup vs baseline: 3.0903x; 1.6190x over previous
#include <cuda_runtime.h>
#include <cuda_fp16.h>
#include <cstdint>

#define N_TOK 4096
#define DM    1024
#define NE    64
#define CAP   512

// ---- scratch (device globals; no allocation allowed) ----
__device__ int    g_cnt[NE];
__device__ int    g_topE[N_TOK * 2];
__device__ float  g_topW[N_TOK * 2];
__device__ int    g_tokid[NE * CAP];
__device__ float  g_tokw[NE * CAP];
__device__ float  g_logits[N_TOK * NE];
__device__ __half g_wh[(size_t)NE * DM * DM];   // 128 MB: pre-converted expert weights
__device__ __half g_ah[(size_t)NE * CAP * DM];  // 64 MB: pre-gathered+converted A rows

__device__ __forceinline__ uint32_t pkh(float a, float b) {
    __half2 h = __floats2half2_rn(a, b);
    return *(uint32_t*)&h;
}

// ---------------------------------------------------------
__global__ void k_init() {
    if (threadIdx.x < NE) g_cnt[threadIdx.x] = 0;
}

// ---- W fp32 -> fp16 streaming convert (8 elems/thread) ----
__global__ __launch_bounds__(256) void k_cvt_w(const float* __restrict__ ew) {
    size_t i = ((size_t)blockIdx.x * 256 + threadIdx.x) * 8;
    float4 v0 = *(const float4*)(ew + i);
    float4 v1 = *(const float4*)(ew + i + 4);
    uint4 o;
    o.x = pkh(v0.x, v0.y); o.y = pkh(v0.z, v0.w);
    o.z = pkh(v1.x, v1.y); o.w = pkh(v1.z, v1.w);
    *(uint4*)(g_wh + i) = o;
}

// ---- gating GEMM: logits[N,E] = x[N,D] @ gate_w[E,D]^T (fp32 SIMT, exact) ----
#define BK  16
#define SMS 68

__global__ __launch_bounds__(256) void k_gate(const float* __restrict__ x,
                                              const float* __restrict__ gw) {
    __shared__ float As[BK][SMS];
    __shared__ float Bs[BK][SMS];
    int t  = threadIdx.x;
    int lr = t >> 2;
    int lc = (t & 3) << 2;
    int m0 = blockIdx.x * 64;
    const float* aptr = x  + (size_t)(m0 + lr) * DM;
    const float* bptr = gw + (size_t)lr * DM;
    int ty = t >> 4, tx = t & 15;
    float acc[4][4] = {};

    for (int k0 = 0; k0 < DM; k0 += BK) {
        float4 av = *(const float4*)(aptr + k0 + lc);
        float4 bv = *(const float4*)(bptr + k0 + lc);
        __syncthreads();
        As[lc][lr] = av.x; As[lc + 1][lr] = av.y; As[lc + 2][lr] = av.z; As[lc + 3][lr] = av.w;
        Bs[lc][lr] = bv.x; Bs[lc + 1][lr] = bv.y; Bs[lc + 2][lr] = bv.z; Bs[lc + 3][lr] = bv.w;
        __syncthreads();
#pragma unroll
        for (int kk = 0; kk < BK; kk++) {
            float4 a4 = *(const float4*)&As[kk][ty * 4];
            float4 b4 = *(const float4*)&Bs[kk][tx * 4];
            float a[4] = {a4.x, a4.y, a4.z, a4.w};
            float b[4] = {b4.x, b4.y, b4.z, b4.w};
#pragma unroll
            for (int i = 0; i < 4; i++)
#pragma unroll
                for (int j = 0; j < 4; j++) acc[i][j] += a[i] * b[j];
        }
    }
#pragma unroll
    for (int i = 0; i < 4; i++) {
        int m = m0 + ty * 4 + i;
        *(float4*)&g_logits[m * NE + tx * 4] =
            make_float4(acc[i][0], acc[i][1], acc[i][2], acc[i][3]);
    }
}

// ---- top-2 + softmax: one warp per token ----
__global__ void k_top2() {
    int gid  = blockIdx.x * blockDim.x + threadIdx.x;
    int tokn = gid >> 5;
    int lane = threadIdx.x & 31;
    if (tokn >= N_TOK) return;
    const float* lg = g_logits + tokn * NE;
    float a = lg[lane], b = lg[lane + 32];
    float v1, v2; int i1, i2;
    if (a >= b) { v1 = a; i1 = lane;      v2 = b; i2 = lane + 32; }
    else        { v1 = b; i1 = lane + 32; v2 = a; i2 = lane;      }
#pragma unroll
    for (int off = 16; off > 0; off >>= 1) {
        float ov1 = __shfl_xor_sync(0xffffffffu, v1, off);
        int   oi1 = __shfl_xor_sync(0xffffffffu, i1, off);
        float ov2 = __shfl_xor_sync(0xffffffffu, v2, off);
        int   oi2 = __shfl_xor_sync(0xffffffffu, i2, off);
        bool og = (ov1 > v1) || (ov1 == v1 && oi1 < i1);
        if (og) {
            bool sg = (v1 > ov2) || (v1 == ov2 && i1 < oi2);
            if (sg) { v2 = v1; i2 = i1; } else { v2 = ov2; i2 = oi2; }
            v1 = ov1; i1 = oi1;
        } else {
            bool sg = (ov1 > v2) || (ov1 == v2 && oi1 < i2);
            if (sg) { v2 = ov1; i2 = oi1; }
        }
    }
    if (lane == 0) {
        float e  = expf(v2 - v1);
        float w1 = 1.0f / (1.0f + e);
        g_topE[tokn * 2]     = i1;
        g_topE[tokn * 2 + 1] = i2;
        g_topW[tokn * 2]     = w1;
        g_topW[tokn * 2 + 1] = e * w1;
    }
}

// ---- dispatch: build per-expert token lists ----
__global__ void k_scatter() {
    int s = blockIdx.x * blockDim.x + threadIdx.x;
    if (s >= N_TOK * 2) return;
    int e   = g_topE[s];
    int pos = atomicAdd(&g_cnt[e], 1);
    if (pos < CAP) {
        g_tokid[e * CAP + pos] = s >> 1;
        g_tokw [e * CAP + pos] = g_topW[s];
    }
}

// ---- pre-gather + convert A rows into per-expert slots (fp16) ----
// 2 rows per 256-thread block; 128 threads per row, 8 floats/thread.
__global__ __launch_bounds__(256) void k_cvt_a(const float* __restrict__ x) {
    int slot = blockIdx.x * 2 + (threadIdx.x >> 7);
    int e = slot >> 9;           // / CAP
    int p = slot & (CAP - 1);
    if (p >= min(g_cnt[e], CAP)) return;    // stale rows harmless (dropped in epilogue)
    int tk = g_tokid[slot];
    int t  = threadIdx.x & 127;
    const float* src = x + (size_t)tk * DM + t * 8;
    float4 v0 = *(const float4*)src;
    float4 v1 = *(const float4*)(src + 4);
    uint4 o;
    o.x = pkh(v0.x, v0.y); o.y = pkh(v0.z, v0.w);
    o.z = pkh(v1.x, v1.y); o.w = pkh(v1.z, v1.w);
    *(uint4*)(g_ah + (size_t)slot * DM + t * 8) = o;
}

// =========================================================
// cp.async 3-stage pipelined fp16 grouped GEMM (fp32 accum)
// CTA tile 128x128, K-chunk 64, 8 warps (2x4), warp tile 64x32.
// SW128-swizzled smem; A,B pre-converted fp16 in global.
// =========================================================

#define SWZ(o) ((o) ^ (((o) >> 3) & 0x70))

#define LDSM4(r0, r1, r2, r3, a)                                             \
    asm volatile("ldmatrix.sync.aligned.m8n8.x4.shared.b16 {%0,%1,%2,%3}, [%4];" \
                 : "=r"(r0), "=r"(r1), "=r"(r2), "=r"(r3) : "r"(a))

#define MMA(d, a, b0, b1)                                                     \
    asm volatile("mma.sync.aligned.m16n8k16.row.col.f32.f16.f16.f32 "         \
                 "{%0,%1,%2,%3},{%4,%5,%6,%7},{%8,%9},{%0,%1,%2,%3};"         \
                 : "+f"((d)[0]), "+f"((d)[1]), "+f"((d)[2]), "+f"((d)[3])     \
                 : "r"((a)[0]), "r"((a)[1]), "r"((a)[2]), "r"((a)[3]),        \
                   "r"(b0), "r"(b1))

#define CPA(sdst, gsrc)                                                       \
    asm volatile("cp.async.cg.shared.global [%0], [%1], 16;"                  \
                 :: "r"(sdst), "l"(gsrc) : "memory")
#define CPCOMMIT() asm volatile("cp.async.commit_group;" ::: "memory")
#define CPWAIT(n)  asm volatile("cp.async.wait_group %0;" :: "n"(n) : "memory")

#define R_B    16384
#define STAGEB 32768
#define SMEM_MOE (1024 + 3 * STAGEB)   // 99328 -> 2 CTAs/SM

__device__ __forceinline__ void issue_chunk(const __half* __restrict__ ab,
                                            const __half* __restrict__ bb,
                                            uint32_t st, int c, int tid) {
    const __half* a = ab + (c << 6);
    const __half* b = bb + (c << 6);
#pragma unroll
    for (int i = 0; i < 4; i++) {
        int idx = (i << 8) + tid;          // 0..1023
        int row = idx >> 3, t16 = idx & 7;
        uint32_t so = SWZ((uint32_t)((row << 7) | (t16 << 4)));
        CPA(st + so,       (const void*)(a + (size_t)row * DM + (t16 << 3)));
        CPA(st + R_B + so, (const void*)(b + (size_t)row * DM + (t16 << 3)));
    }
    CPCOMMIT();
}

__global__ __launch_bounds__(256, 2) void k_moe(float* __restrict__ out) {
    extern __shared__ __align__(1024) char smem[];
    int*   toks = (int*)smem;            // 512 B
    float* wts  = (float*)(smem + 512);  // 512 B
    char*  buf  = smem + 1024;           // 3 x 32 KB

    int e    = blockIdx.x >> 2;
    int mt   = blockIdx.x & 3;
    int cnt  = min(g_cnt[e], CAP);
    int row0 = mt << 7;
    if (row0 >= cnt) return;
    int n0   = blockIdx.y << 7;

    int tid = threadIdx.x, lane = tid & 31, wid = tid >> 5;
    int mw = wid & 1, nw = wid >> 1;

    if (tid < 128) {
        int r = row0 + tid;
        bool v = r < cnt;
        toks[tid] = v ? g_tokid[e * CAP + r] : -1;
        wts[tid]  = v ? g_tokw[e * CAP + r] : 0.0f;
    }

    const __half* ab = g_ah + ((size_t)(e * CAP + row0)) * DM;
    const __half* bb = g_wh + ((size_t)e << 20) + ((size_t)n0 << 10);

    uint32_t sbuf;
    asm("{ .reg .u64 t; cvta.to.shared.u64 t, %1; cvt.u32.u64 %0, t; }"
        : "=r"(sbuf) : "l"(buf));

    // ldmatrix per-lane row offsets (validated R3/R4)
    uint32_t a_ro = (uint32_t)(((mw << 6) + (lane & 15)) << 7) + (uint32_t)((lane >> 4) << 4);
    uint32_t b_ro = (uint32_t)(((nw << 5) + (lane & 7) + ((lane >> 4) << 3)) << 7)
                  + (uint32_t)(((lane >> 3) & 1) << 4);

    float acc[4][4][4];
#pragma unroll
    for (int i = 0; i < 4; i++)
#pragma unroll
        for (int j = 0; j < 4; j++)
#pragma unroll
            for (int q = 0; q < 4; q++) acc[i][j][q] = 0.0f;

    // prologue: 2 chunks in flight
    issue_chunk(ab, bb, sbuf,              0, tid);
    issue_chunk(ab, bb, sbuf + STAGEB,     1, tid);

    int stage = 0;
    for (int c = 0; c < 16; c++) {
        if (c >= 14) CPWAIT(0); else CPWAIT(1);   // chunk c resident
        __syncthreads();                          // visibility + LDSM(c-1) done
        if (c + 2 < 16) {
            int ns = stage + 2; if (ns >= 3) ns -= 3;
            issue_chunk(ab, bb, sbuf + (uint32_t)ns * STAGEB, c + 2, tid);
        }
        uint32_t cb = sbuf + (uint32_t)stage * STAGEB;

#pragma unroll
        for (int ks = 0; ks < 4; ks++) {
            uint32_t kb = (uint32_t)(ks << 5);
            uint32_t bh[8];
#pragma unroll
            for (int j2 = 0; j2 < 2; j2++) {
                uint32_t o = SWZ(b_ro + (uint32_t)(j2 << 11) + kb);
                LDSM4(bh[j2 * 4], bh[j2 * 4 + 1], bh[j2 * 4 + 2], bh[j2 * 4 + 3],
                      cb + R_B + o);
            }
#pragma unroll
            for (int i = 0; i < 4; i++) {
                uint32_t o = SWZ(a_ro + (uint32_t)(i << 11) + kb);
                uint32_t ah[4];
                LDSM4(ah[0], ah[1], ah[2], ah[3], cb + o);
#pragma unroll
                for (int j = 0; j < 4; j++)
                    MMA(acc[i][j], ah, bh[j * 2], bh[j * 2 + 1]);
            }
        }
        stage++; if (stage >= 3) stage = 0;
    }

    // ---- epilogue: scale by gate weight, atomicAdd combine ----
    int l4 = lane >> 2;
    int l2 = (lane & 3) << 1;
#pragma unroll
    for (int i = 0; i < 4; i++) {
        int r0 = (mw << 6) + (i << 4) + l4;
        int r1 = r0 + 8;
        int   tk0 = toks[r0]; float w0 = wts[r0];
        int   tk1 = toks[r1]; float w1 = wts[r1];
        float* o0 = out + (size_t)(tk0 < 0 ? 0 : tk0) * DM;
        float* o1 = out + (size_t)(tk1 < 0 ? 0 : tk1) * DM;
#pragma unroll
        for (int j = 0; j < 4; j++) {
            int nb = n0 + (nw << 5) + (j << 3) + l2;
            if (tk0 >= 0) {
                atomicAdd(o0 + nb,     w0 * acc[i][j][0]);
                atomicAdd(o0 + nb + 1, w0 * acc[i][j][1]);
            }
            if (tk1 >= 0) {
                atomicAdd(o1 + nb,     w1 * acc[i][j][2]);
                atomicAdd(o1 + nb + 1, w1 * acc[i][j][3]);
            }
        }
    }
}

// ---------------------------------------------------------
extern "C" void kernel_launch(void* const* d_in, const int* in_sizes, int n_in,
                              void* d_out, int out_size) {
    const float* x  = (const float*)d_in[0];   // [4096,1024]
    const float* gw = (const float*)d_in[1];   // [64,1024]
    const float* ew = (const float*)d_in[2];   // [64,1024,1024]
    float* out = (float*)d_out;                // [4096,1024]

    cudaFuncSetAttribute(k_moe, cudaFuncAttributeMaxDynamicSharedMemorySize, SMEM_MOE);

    cudaMemsetAsync(d_out, 0, (size_t)N_TOK * DM * sizeof(float), 0);
    k_init<<<1, 64>>>();
    k_cvt_w<<<(NE * DM * DM) / (256 * 8), 256>>>(ew);
    k_gate<<<N_TOK / 64, 256>>>(x, gw);
    k_top2<<<N_TOK / 8, 256>>>();
    k_scatter<<<(N_TOK * 2) / 256, 256>>>();
    k_cvt_a<<<(NE * CAP) / 2, 256>>>(x);
    dim3 grid(NE * 4, DM / 128);
    k_moe<<<grid, 256, SMEM_MOE>>>(out);
    (void)in_sizes; (void)n_in; (void)out_size;
}

// round 6
// speedup vs baseline: 3.1093x; 1.0062x over previous
#include <cuda_runtime.h>
#include <cuda_fp16.h>
#include <cstdint>

#define N_TOK 4096
#define DM    1024
#define NE    64
#define CAP   512

// ---- scratch (device globals; no allocation allowed) ----
__device__ int    g_cnt[NE];
__device__ int    g_topE[N_TOK * 2];
__device__ float  g_topW[N_TOK * 2];
__device__ int    g_tokid[NE * CAP];
__device__ float  g_tokw[NE * CAP];
__device__ float  g_logits[N_TOK * NE];
__device__ __half g_ah[(size_t)NE * CAP * DM];  // 64 MB: pre-gathered+converted A rows

__device__ __forceinline__ uint32_t pkh(float a, float b) {
    __half2 h = __floats2half2_rn(a, b);
    return *(uint32_t*)&h;
}

// ---------------------------------------------------------
__global__ void k_init() {
    if (threadIdx.x < NE) g_cnt[threadIdx.x] = 0;
}

// ---- gating GEMM: logits[N,E] = x[N,D] @ gate_w[E,D]^T (fp32 SIMT, exact)
//      32-row tiles -> 128 CTAs for occupancy ----
#define BK 16

__global__ __launch_bounds__(256) void k_gate(const float* __restrict__ x,
                                              const float* __restrict__ gw) {
    __shared__ float As[BK][34];
    __shared__ float Bs[BK][68];
    int t  = threadIdx.x;
    int m0 = blockIdx.x * 32;
    int arow = t >> 3, ak = (t & 7) << 1;
    int brow = t >> 2, bk = (t & 3) << 2;
    const float* aptr = x  + (size_t)(m0 + arow) * DM;
    const float* bptr = gw + (size_t)brow * DM;
    int ty = t >> 4, tx = t & 15;
    float acc[2][4] = {};

    for (int k0 = 0; k0 < DM; k0 += BK) {
        float2 av = *(const float2*)(aptr + k0 + ak);
        float4 bv = *(const float4*)(bptr + k0 + bk);
        __syncthreads();
        As[ak][arow] = av.x; As[ak + 1][arow] = av.y;
        Bs[bk][brow] = bv.x; Bs[bk + 1][brow] = bv.y;
        Bs[bk + 2][brow] = bv.z; Bs[bk + 3][brow] = bv.w;
        __syncthreads();
#pragma unroll
        for (int kk = 0; kk < BK; kk++) {
            float2 a2 = *(const float2*)&As[kk][ty * 2];
            float4 b4 = *(const float4*)&Bs[kk][tx * 4];
            float a[2] = {a2.x, a2.y};
            float b[4] = {b4.x, b4.y, b4.z, b4.w};
#pragma unroll
            for (int i = 0; i < 2; i++)
#pragma unroll
                for (int j = 0; j < 4; j++) acc[i][j] += a[i] * b[j];
        }
    }
#pragma unroll
    for (int i = 0; i < 2; i++) {
        int m = m0 + ty * 2 + i;
        *(float4*)&g_logits[m * NE + tx * 4] =
            make_float4(acc[i][0], acc[i][1], acc[i][2], acc[i][3]);
    }
}

// ---- top-2 + softmax: one warp per token ----
__global__ void k_top2() {
    int gid  = blockIdx.x * blockDim.x + threadIdx.x;
    int tokn = gid >> 5;
    int lane = threadIdx.x & 31;
    if (tokn >= N_TOK) return;
    const float* lg = g_logits + tokn * NE;
    float a = lg[lane], b = lg[lane + 32];
    float v1, v2; int i1, i2;
    if (a >= b) { v1 = a; i1 = lane;      v2 = b; i2 = lane + 32; }
    else        { v1 = b; i1 = lane + 32; v2 = a; i2 = lane;      }
#pragma unroll
    for (int off = 16; off > 0; off >>= 1) {
        float ov1 = __shfl_xor_sync(0xffffffffu, v1, off);
        int   oi1 = __shfl_xor_sync(0xffffffffu, i1, off);
        float ov2 = __shfl_xor_sync(0xffffffffu, v2, off);
        int   oi2 = __shfl_xor_sync(0xffffffffu, i2, off);
        bool og = (ov1 > v1) || (ov1 == v1 && oi1 < i1);
        if (og) {
            bool sg = (v1 > ov2) || (v1 == ov2 && i1 < oi2);
            if (sg) { v2 = v1; i2 = i1; } else { v2 = ov2; i2 = oi2; }
            v1 = ov1; i1 = oi1;
        } else {
            bool sg = (ov1 > v2) || (ov1 == v2 && oi1 < i2);
            if (sg) { v2 = ov1; i2 = oi1; }
        }
    }
    if (lane == 0) {
        float e  = expf(v2 - v1);
        float w1 = 1.0f / (1.0f + e);
        g_topE[tokn * 2]     = i1;
        g_topE[tokn * 2 + 1] = i2;
        g_topW[tokn * 2]     = w1;
        g_topW[tokn * 2 + 1] = e * w1;
    }
}

// ---- dispatch: build per-expert token lists ----
__global__ void k_scatter() {
    int s = blockIdx.x * blockDim.x + threadIdx.x;
    if (s >= N_TOK * 2) return;
    int e   = g_topE[s];
    int pos = atomicAdd(&g_cnt[e], 1);
    if (pos < CAP) {
        g_tokid[e * CAP + pos] = s >> 1;
        g_tokw [e * CAP + pos] = g_topW[s];
    }
}

// ---- pre-gather + convert A rows into per-expert slots (fp16) ----
__global__ __launch_bounds__(256) void k_cvt_a(const float* __restrict__ x) {
    int slot = blockIdx.x * 2 + (threadIdx.x >> 7);
    int e = slot >> 9;
    int p = slot & (CAP - 1);
    if (p >= min(g_cnt[e], CAP)) return;
    int tk = g_tokid[slot];
    int t  = threadIdx.x & 127;
    const float* src = x + (size_t)tk * DM + t * 8;
    float4 v0 = *(const float4*)src;
    float4 v1 = *(const float4*)(src + 4);
    uint4 o;
    o.x = pkh(v0.x, v0.y); o.y = pkh(v0.z, v0.w);
    o.z = pkh(v1.x, v1.y); o.w = pkh(v1.z, v1.w);
    *(uint4*)(g_ah + (size_t)slot * DM + t * 8) = o;
}

// =========================================================
// cp.async 3-stage pipelined fp16 grouped GEMM, W converted
// fp32->fp16 in-kernel (smem bounce). CTA tile 128x128,
// K-chunk 32, 8 warps (2x4), warp tile 64x32.
// A: fp16 SW64 rows (64B); Bf32: SW128 rows (128B); Bf16: SW64.
// =========================================================

#define SWZ(o)   ((o) ^ (((o) >> 3) & 0x70))
#define SWZ64(o) ((o) ^ (((o) >> 3) & 0x30))

#define LDSM4(r0, r1, r2, r3, a)                                             \
    asm volatile("ldmatrix.sync.aligned.m8n8.x4.shared.b16 {%0,%1,%2,%3}, [%4];" \
                 : "=r"(r0), "=r"(r1), "=r"(r2), "=r"(r3) : "r"(a))

#define MMA(d, a, b0, b1)                                                     \
    asm volatile("mma.sync.aligned.m16n8k16.row.col.f32.f16.f16.f32 "         \
                 "{%0,%1,%2,%3},{%4,%5,%6,%7},{%8,%9},{%0,%1,%2,%3};"         \
                 : "+f"((d)[0]), "+f"((d)[1]), "+f"((d)[2]), "+f"((d)[3])     \
                 : "r"((a)[0]), "r"((a)[1]), "r"((a)[2]), "r"((a)[3]),        \
                   "r"(b0), "r"(b1))

#define CPA(sdst, gsrc)                                                       \
    asm volatile("cp.async.cg.shared.global [%0], [%1], 16;"                  \
                 :: "r"(sdst), "l"(gsrc) : "memory")
#define CPCOMMIT() asm volatile("cp.async.commit_group;" ::: "memory")
#define CPWAIT(n)  asm volatile("cp.async.wait_group %0;" :: "n"(n) : "memory")

// smem map (bytes): meta 1024 | A stages 3x8K | Bf32 stages 3x16K | Bf16 8K
#define OFF_A    1024
#define A_ST     8192
#define OFF_B32  (OFF_A + 3 * A_ST)        // 25600
#define B32_ST   16384
#define OFF_B16  (OFF_B32 + 3 * B32_ST)    // 74752
#define SMEM_MOE (OFF_B16 + 8192)          // 82944 -> 2 CTAs/SM

__device__ __forceinline__ void issue_chunk(const __half* __restrict__ ab,
                                            const float* __restrict__ bb,
                                            uint32_t sb, int st, int c, int tid) {
    int row = tid >> 1;
    const __half* a = ab + (size_t)row * DM + (c << 5);
    const float*  b = bb + (size_t)row * DM + (c << 5);
    uint32_t adst = sb + OFF_A + (uint32_t)st * A_ST;
    uint32_t bdst = sb + OFF_B32 + (uint32_t)st * B32_ST;
#pragma unroll
    for (int i = 0; i < 2; i++) {          // A: 2 x 16B per thread
        int u = ((tid & 1) << 1) + i;
        CPA(adst + SWZ64((uint32_t)((row << 6) | (u << 4))), (const void*)(a + (u << 3)));
    }
#pragma unroll
    for (int i = 0; i < 4; i++) {          // B fp32: 4 x 16B per thread
        int u = ((tid & 1) << 2) + i;
        CPA(bdst + SWZ((uint32_t)((row << 7) | (u << 4))), (const void*)(b + (u << 2)));
    }
    CPCOMMIT();
}

__global__ __launch_bounds__(256, 2) void k_moe(const float* __restrict__ ew,
                                                float* __restrict__ out) {
    extern __shared__ __align__(1024) char smem[];
    int*   toks = (int*)smem;            // 512 B
    float* wts  = (float*)(smem + 512);  // 512 B

    int e    = blockIdx.x >> 2;
    int mt   = blockIdx.x & 3;
    int cnt  = min(g_cnt[e], CAP);
    int row0 = mt << 7;
    if (row0 >= cnt) return;
    int n0   = blockIdx.y << 7;

    int tid = threadIdx.x, lane = tid & 31, wid = tid >> 5;
    int mw = wid & 1, nw = wid >> 1;

    if (tid < 128) {
        int r = row0 + tid;
        bool v = r < cnt;
        toks[tid] = v ? g_tokid[e * CAP + r] : -1;
        wts[tid]  = v ? g_tokw[e * CAP + r] : 0.0f;
    }

    const __half* ab = g_ah + ((size_t)(e * CAP + row0)) * DM;
    const float*  bb = ew + ((size_t)e << 20) + ((size_t)n0 << 10);

    uint32_t sb;
    asm("{ .reg .u64 t; cvta.to.shared.u64 t, %1; cvt.u32.u64 %0, t; }"
        : "=r"(sb) : "l"(smem));

    // ldmatrix per-lane offsets for 64B-row SW64 tiles
    uint32_t a_ro = (uint32_t)(((mw << 6) + (lane & 15)) << 6) + (uint32_t)((lane >> 4) << 4);
    uint32_t b_ro = (uint32_t)(((nw << 5) + (lane & 7) + ((lane >> 4) << 3)) << 6)
                  + (uint32_t)(((lane >> 3) & 1) << 4);
    uint32_t b16 = sb + OFF_B16;

    // convert-phase addressing (this thread's share of the B fp32 stage)
    int crow = tid >> 1;
    int cbase = (tid & 1) << 2;

    float acc[4][4][4];
#pragma unroll
    for (int i = 0; i < 4; i++)
#pragma unroll
        for (int j = 0; j < 4; j++)
#pragma unroll
            for (int q = 0; q < 4; q++) acc[i][j][q] = 0.0f;

    issue_chunk(ab, bb, sb, 0, 0, tid);
    issue_chunk(ab, bb, sb, 1, 1, tid);

    int stage = 0;
    for (int c = 0; c < 32; c++) {
        if (c + 1 < 32) CPWAIT(1); else CPWAIT(0);
        __syncthreads();                       // chunk c resident; prev reads done
        if (c + 2 < 32) {
            int ns = stage + 2; if (ns >= 3) ns -= 3;
            issue_chunk(ab, bb, sb, ns, c + 2, tid);
        }
        // --- convert B fp32 (stage) -> fp16 bounce buffer ---
        {
            char* bsrc = smem + OFF_B32 + stage * B32_ST;
#pragma unroll
            for (int j = 0; j < 2; j++) {
                uint32_t u0 = (uint32_t)(cbase + 2 * j);
                float4 f0 = *(const float4*)(bsrc + SWZ((uint32_t)((crow << 7) | (u0 << 4))));
                float4 f1 = *(const float4*)(bsrc + SWZ((uint32_t)((crow << 7) | ((u0 + 1) << 4))));
                uint4 o;
                o.x = pkh(f0.x, f0.y); o.y = pkh(f0.z, f0.w);
                o.z = pkh(f1.x, f1.y); o.w = pkh(f1.z, f1.w);
                uint32_t v = (uint32_t)((tid & 1) * 2 + j);
                *(uint4*)(smem + OFF_B16 + SWZ64((uint32_t)((crow << 6) | (v << 4)))) = o;
            }
        }
        __syncthreads();                       // fp16 B visible
        uint32_t ca = sb + OFF_A + (uint32_t)stage * A_ST;

#pragma unroll
        for (int ks = 0; ks < 2; ks++) {
            uint32_t kb = (uint32_t)(ks << 5);
            uint32_t bh[8];
#pragma unroll
            for (int j2 = 0; j2 < 2; j2++) {
                uint32_t o = SWZ64(b_ro + (uint32_t)(j2 << 10) + kb);
                LDSM4(bh[j2 * 4], bh[j2 * 4 + 1], bh[j2 * 4 + 2], bh[j2 * 4 + 3],
                      b16 + o);
            }
#pragma unroll
            for (int i = 0; i < 4; i++) {
                uint32_t o = SWZ64(a_ro + (uint32_t)(i << 10) + kb);
                uint32_t ah[4];
                LDSM4(ah[0], ah[1], ah[2], ah[3], ca + o);
#pragma unroll
                for (int j = 0; j < 4; j++)
                    MMA(acc[i][j], ah, bh[j * 2], bh[j * 2 + 1]);
            }
        }
        stage++; if (stage >= 3) stage = 0;
    }

    // ---- epilogue: scale by gate weight, atomicAdd combine ----
    int l4 = lane >> 2;
    int l2 = (lane & 3) << 1;
#pragma unroll
    for (int i = 0; i < 4; i++) {
        int r0 = (mw << 6) + (i << 4) + l4;
        int r1 = r0 + 8;
        int   tk0 = toks[r0]; float w0 = wts[r0];
        int   tk1 = toks[r1]; float w1 = wts[r1];
        float* o0 = out + (size_t)(tk0 < 0 ? 0 : tk0) * DM;
        float* o1 = out + (size_t)(tk1 < 0 ? 0 : tk1) * DM;
#pragma unroll
        for (int j = 0; j < 4; j++) {
            int nb = n0 + (nw << 5) + (j << 3) + l2;
            if (tk0 >= 0) {
                atomicAdd(o0 + nb,     w0 * acc[i][j][0]);
                atomicAdd(o0 + nb + 1, w0 * acc[i][j][1]);
            }
            if (tk1 >= 0) {
                atomicAdd(o1 + nb,     w1 * acc[i][j][2]);
                atomicAdd(o1 + nb + 1, w1 * acc[i][j][3]);
            }
        }
    }
}

// ---------------------------------------------------------
extern "C" void kernel_launch(void* const* d_in, const int* in_sizes, int n_in,
                              void* d_out, int out_size) {
    const float* x  = (const float*)d_in[0];   // [4096,1024]
    const float* gw = (const float*)d_in[1];   // [64,1024]
    const float* ew = (const float*)d_in[2];   // [64,1024,1024]
    float* out = (float*)d_out;                // [4096,1024]

    cudaFuncSetAttribute(k_moe, cudaFuncAttributeMaxDynamicSharedMemorySize, SMEM_MOE);

    cudaMemsetAsync(d_out, 0, (size_t)N_TOK * DM * sizeof(float), 0);
    k_init<<<1, 64>>>();
    k_gate<<<N_TOK / 32, 256>>>(x, gw);
    k_top2<<<N_TOK / 8, 256>>>();
    k_scatter<<<(N_TOK * 2) / 256, 256>>>();
    k_cvt_a<<<(NE * CAP) / 2, 256>>>(x);
    dim3 grid(NE * 4, DM / 128);
    k_moe<<<grid, 256, SMEM_MOE>>>(ew, out);
    (void)in_sizes; (void)n_in; (void)out_size;
}